// round 17
// baseline (speedup 1.0000x reference)
#include <cuda_runtime.h>
#include <cuda_fp16.h>
#include <cuda_bf16.h>

// ---------------------------------------------------------------------------
// HierarchicalConsistencyLoss:
//   diff = offset_inst - offset_tree          (coords cancels, never loaded)
//   per-tree sums of (diff, 1) for labels > 0; loss =
//   sum_t ||sum_t/c_t||^2 [c_t>=2]  /  #{t : c_t>=1}
//
// R16 = R15 resubmitted (previous round failed on container infra, the
// kernel never ran). EARLY PDL TRIGGER via persistent grid: the trigger
// fires only after ALL primary CTAs execute it; with a one-shot grid that
// is the very end, so finalize's launch was never overlapped (tail stuck
// at ~8us). Now: accum is a persistent 592-CTA grid-stride kernel whose
// FIRST statement is cudaTriggerProgrammaticLaunchCompletion() — all CTAs
// start in wave 1, the trigger fires ~us after launch, and the finalize
// grid pre-launches and spins in cudaGridDependencySynchronize() (which
// still guarantees accum completion + visibility). Exposed tail ->
// finalize work + drain. NREP ladder saturated (kept at 256). No fence in
// accum (in-kernel device fences measured +13..21us — permanently dead).
// ---------------------------------------------------------------------------

#define NBINS 1024    // T=1000 padded to power of two
#define NREP  256     // 256*1024*8B = 2MB, L2-resident
#define ACC_CTAS 592  // persistent grid: ~4 CTAs/SM, all resident in wave 1
#define FIN_CTAS 128
#define FIN_THR  256
#define TREES_PER_CTA 8   // FIN_CTAS * TREES_PER_CTA = NBINS

// per-bin packed accumulator: .x = f16x2(sum_x,sum_y), .y = f16x2(sum_z,count)
// zero-initialized at module load; finalize re-zeroes after each use.
__device__ uint2 g_bins16[NREP * NBINS];
__device__ float g_tot;                  // cross-CTA partial (reset each use)
__device__ float g_cnt;
__device__ unsigned int g_ticket;

__device__ __forceinline__ void red_h2v2(uint2* p, float dx, float dy, float dz) {
    __half2 xy = __floats2half2_rn(dx, dy);
    __half2 zc = __floats2half2_rn(dz, 1.0f);
    asm volatile("red.global.add.noftz.v2.f16x2 [%0], {%1, %2};"
                 :: "l"(p),
                    "r"(*reinterpret_cast<unsigned int*>(&xy)),
                    "r"(*reinterpret_cast<unsigned int*>(&zc))
                 : "memory");
}

__global__ void __launch_bounds__(256)
accum_kernel(const float4* __restrict__ oi,   // offset_inst as float4 stream
             const float4* __restrict__ ot,   // offset_tree as float4 stream
             const int4*   __restrict__ lab,  // labels as int4 stream
             int nquad,                        // number of 4-point groups
             const float* __restrict__ oi_s,  // scalar views for the tail
             const float* __restrict__ ot_s,
             const int*   __restrict__ lab_s,
             int n)                            // total points
{
    // Fire the PDL trigger IMMEDIATELY: all CTAs are resident in wave 1,
    // so the secondary (finalize) launches ~us after we start and spins in
    // cudaGridDependencySynchronize() — which still waits for our full
    // completion + memory visibility. Launch latency fully hidden.
    cudaTriggerProgrammaticLaunchCompletion();

    // replica: warp id in low 3 bits (co-resident warps distinct),
    // multiplicative block mix in the upper bits
    int rep = ((threadIdx.x >> 5) + blockIdx.x * 37) & (NREP - 1);
    uint2* bins = g_bins16 + rep * NBINS;

    int stride = gridDim.x * blockDim.x;
    for (int i = blockIdx.x * blockDim.x + threadIdx.x; i < nquad; i += stride) {
        // 4 points = 12 floats = 3 float4 per array + 1 int4 of labels
        int base = 3 * i;
        float4 a0 = __ldcs(&oi[base + 0]);
        float4 a1 = __ldcs(&oi[base + 1]);
        float4 a2 = __ldcs(&oi[base + 2]);
        float4 b0 = __ldcs(&ot[base + 0]);
        float4 b1 = __ldcs(&ot[base + 1]);
        float4 b2 = __ldcs(&ot[base + 2]);
        int4 L  = __ldcs(&lab[i]);

        // branch-free: label 0 hits bin 0, which finalize ignores
        red_h2v2(&bins[L.x], a0.x - b0.x, a0.y - b0.y, a0.z - b0.z);
        red_h2v2(&bins[L.y], a0.w - b0.w, a1.x - b1.x, a1.y - b1.y);
        red_h2v2(&bins[L.z], a1.z - b1.z, a1.w - b1.w, a2.x - b2.x);
        red_h2v2(&bins[L.w], a2.y - b2.y, a2.z - b2.z, a2.w - b2.w);
    }
    // tail points (n % 4) — N=4M so empty in practice
    if (blockIdx.x == 0 && threadIdx.x == 0) {
        for (int p = (n / 4) * 4; p < n; ++p) {
            int l = lab_s[p];
            red_h2v2(&g_bins16[l],
                     oi_s[3 * p + 0] - ot_s[3 * p + 0],
                     oi_s[3 * p + 1] - ot_s[3 * p + 1],
                     oi_s[3 * p + 2] - ot_s[3 * p + 2]);
        }
    }
}

// Full-width finalize: CTA c owns trees [8c, 8c+8). Thread tid=(r*8+j)
// folds replicas r + k*32 of tree 8c+j, zero-stores them, smem-combines
// per tree, CTA partial (tot,cnt) -> global pair; last CTA (ticket) writes
// the output and resets state for the next graph replay.
__global__ void __launch_bounds__(FIN_THR)
finalize_kernel(float* __restrict__ out) {
    cudaGridDependencySynchronize();   // PDL: wait for accum + visibility

    __shared__ float4 s_part[FIN_THR];
    __shared__ float2 s_tree[TREES_PER_CTA];

    int tid = threadIdx.x;
    int r = tid >> 3;                  // base replica 0..31
    int j = tid & 7;                   // local tree 0..7
    int t = blockIdx.x * TREES_PER_CTA + j;

    float sx = 0.f, sy = 0.f, sz = 0.f, c = 0.f;
    #pragma unroll
    for (int k = 0; k < NREP / 32; ++k) {
        int rr = r + k * 32;
        uint2 b = g_bins16[rr * NBINS + t];
        float2 xy = __half22float2(*reinterpret_cast<__half2*>(&b.x));
        float2 zc = __half22float2(*reinterpret_cast<__half2*>(&b.y));
        sx += xy.x; sy += xy.y; sz += zc.x; c += zc.y;
    }
    // self-clean after all loads
    #pragma unroll
    for (int k = 0; k < NREP / 32; ++k)
        g_bins16[(r + k * 32) * NBINS + t] = make_uint2(0u, 0u);

    s_part[tid] = make_float4(sx, sy, sz, c);
    __syncthreads();

    if (tid < TREES_PER_CTA) {
        float tx = 0.f, ty = 0.f, tz = 0.f, tc = 0.f;
        #pragma unroll
        for (int rr = 0; rr < 32; ++rr) {
            float4 p = s_part[rr * 8 + tid];
            tx += p.x; ty += p.y; tz += p.z; tc += p.w;
        }
        float tot = 0.f, ntree = 0.f;
        int tree = blockIdx.x * TREES_PER_CTA + tid;
        if (tree >= 1 && tree < 1000) {  // label 0 = stuff; 1000.. padding
            if (tc >= 1.f) ntree = 1.f;
            if (tc >= 2.f) {
                float inv = 1.f / tc;
                float mx = tx * inv, my = ty * inv, mz = tz * inv;
                tot = mx * mx + my * my + mz * mz;
            }
        }
        s_tree[tid] = make_float2(tot, ntree);
    }
    __syncthreads();

    if (tid == 0) {
        float T = 0.f, C = 0.f;
        #pragma unroll
        for (int k = 0; k < TREES_PER_CTA; ++k) {
            T += s_tree[k].x; C += s_tree[k].y;
        }
        atomicAdd(&g_tot, T);
        atomicAdd(&g_cnt, C);
        __threadfence();
        unsigned int prev = atomicAdd(&g_ticket, 1u);
        if (prev == FIN_CTAS - 1) {
            __threadfence();  // acquire: order reads after final ticket
            float FT = atomicAdd(&g_tot, 0.f);   // L2-coherent read
            float FC = atomicAdd(&g_cnt, 0.f);
            out[0] = (FC > 0.f) ? (FT / FC) : 0.f;
            g_tot = 0.f;       // reset for next replay
            g_cnt = 0.f;
            g_ticket = 0u;
        }
    }
}

extern "C" void kernel_launch(void* const* d_in, const int* in_sizes, int n_in,
                              void* d_out, int out_size) {
    // metadata order: coords, offset_inst, offset_tree, tree_labels
    const float* oi_s  = (const float*)d_in[1];
    const float* ot_s  = (const float*)d_in[2];
    const int*   lab_s = (const int*)d_in[3];
    int n = in_sizes[3];

    int nquad  = n / 4;
    int needed = (nquad + 255) / 256;
    int blocks = needed < ACC_CTAS ? needed : ACC_CTAS;
    if (blocks < 1) blocks = 1;

    accum_kernel<<<blocks, 256>>>((const float4*)oi_s, (const float4*)ot_s,
                                  (const int4*)lab_s, nquad,
                                  oi_s, ot_s, lab_s, n);

    cudaLaunchAttribute attrs[1];
    attrs[0].id = cudaLaunchAttributeProgrammaticStreamSerialization;
    attrs[0].val.programmaticStreamSerializationAllowed = 1;

    cudaLaunchConfig_t cfg = {};
    cfg.gridDim  = dim3(FIN_CTAS, 1, 1);
    cfg.blockDim = dim3(FIN_THR, 1, 1);
    cfg.dynamicSmemBytes = 0;
    cfg.stream = 0;
    cfg.attrs = attrs;
    cfg.numAttrs = 1;

    float* out = (float*)d_out;
    cudaLaunchKernelEx(&cfg, finalize_kernel, out);
}